// round 1
// baseline (speedup 1.0000x reference)
#include <cuda_runtime.h>

#define ND 128
#define HID 16
#define N_MAX 100000
#define MLP_BLOCK 128
#define MLP_GRID_MAX ((N_MAX + MLP_BLOCK - 1) / MLP_BLOCK)

// Scratch (no device allocs allowed)
__device__ float g_deg[N_MAX];
__device__ float g_w[N_MAX];
__device__ float g_part[MLP_GRID_MAX * HID];

__device__ __forceinline__ float ftanh(float v) {
    // tanh(x) = 1 - 2/(exp(2x)+1); exact at saturation, ~1e-6 error elsewhere
    return 1.0f - __fdividef(2.0f, __expf(2.0f * v) + 1.0f);
}

__global__ void zero_kernel(int n) {
    int i = blockIdx.x * blockDim.x + threadIdx.x;
    if (i < n) { g_deg[i] = 0.0f; g_w[i] = 0.0f; }
}

__global__ void deg_kernel(const int* __restrict__ src, int e) {
    int i = blockIdx.x * blockDim.x + threadIdx.x;
    if (i < e) atomicAdd(&g_deg[src[i]], 1.0f);
}

__global__ void w_kernel(const int* __restrict__ src, const int* __restrict__ dst, int e) {
    int i = blockIdx.x * blockDim.x + threadIdx.x;
    if (i < e) {
        float d = g_deg[src[i]];           // >= 1 by construction (src appears in an edge)
        atomicAdd(&g_w[dst[i]], 1.0f / d);
    }
}

__global__ void __launch_bounds__(MLP_BLOCK) mlp_kernel(
    const float* __restrict__ x,
    const float* __restrict__ W1, const float* __restrict__ b1,
    const float* __restrict__ W2, const float* __restrict__ b2,
    const float* __restrict__ W3, const float* __restrict__ b3,
    int n)
{
    __shared__ float sW1[ND * HID];
    __shared__ float sW2[HID * HID];
    __shared__ float sW3[HID * HID];
    __shared__ float sb1[HID], sb2[HID], sb3[HID];
    __shared__ float sRed[(MLP_BLOCK / 32) * HID];

    int tid = threadIdx.x;
    for (int i = tid; i < ND * HID; i += MLP_BLOCK) sW1[i] = W1[i];
    for (int i = tid; i < HID * HID; i += MLP_BLOCK) { sW2[i] = W2[i]; sW3[i] = W3[i]; }
    if (tid < HID) { sb1[tid] = b1[tid]; sb2[tid] = b2[tid]; sb3[tid] = b3[tid]; }
    __syncthreads();

    int node = blockIdx.x * MLP_BLOCK + tid;
    float acc[HID];
#pragma unroll
    for (int j = 0; j < HID; j++) acc[j] = 0.0f;

    if (node < n) {
        // ---- layer 1: 128 -> 16 ----
        float h1[HID];
#pragma unroll
        for (int j = 0; j < HID; j++) h1[j] = sb1[j];

        const float4* xr = reinterpret_cast<const float4*>(x + (size_t)node * ND);
#pragma unroll 4
        for (int k4 = 0; k4 < ND / 4; k4++) {
            float4 xv = xr[k4];
            float xs[4] = {xv.x, xv.y, xv.z, xv.w};
#pragma unroll
            for (int i = 0; i < 4; i++) {
                const float4* wr = reinterpret_cast<const float4*>(sW1 + (k4 * 4 + i) * HID);
#pragma unroll
                for (int q = 0; q < 4; q++) {
                    float4 ww = wr[q];
                    h1[q * 4 + 0] += xs[i] * ww.x;
                    h1[q * 4 + 1] += xs[i] * ww.y;
                    h1[q * 4 + 2] += xs[i] * ww.z;
                    h1[q * 4 + 3] += xs[i] * ww.w;
                }
            }
        }
#pragma unroll
        for (int j = 0; j < HID; j++) h1[j] = ftanh(h1[j]);

        // ---- layer 2: 16 -> 16 ----
        float h2[HID];
#pragma unroll
        for (int j = 0; j < HID; j++) h2[j] = sb2[j];
#pragma unroll
        for (int i = 0; i < HID; i++) {
            float hv = h1[i];
            const float4* wr = reinterpret_cast<const float4*>(sW2 + i * HID);
#pragma unroll
            for (int q = 0; q < 4; q++) {
                float4 ww = wr[q];
                h2[q * 4 + 0] += hv * ww.x;
                h2[q * 4 + 1] += hv * ww.y;
                h2[q * 4 + 2] += hv * ww.z;
                h2[q * 4 + 3] += hv * ww.w;
            }
        }
#pragma unroll
        for (int j = 0; j < HID; j++) h2[j] = ftanh(h2[j]);

        // ---- layer 3: 16 -> 16 ----
        float h3[HID];
#pragma unroll
        for (int j = 0; j < HID; j++) h3[j] = sb3[j];
#pragma unroll
        for (int i = 0; i < HID; i++) {
            float hv = h2[i];
            const float4* wr = reinterpret_cast<const float4*>(sW3 + i * HID);
#pragma unroll
            for (int q = 0; q < 4; q++) {
                float4 ww = wr[q];
                h3[q * 4 + 0] += hv * ww.x;
                h3[q * 4 + 1] += hv * ww.y;
                h3[q * 4 + 2] += hv * ww.z;
                h3[q * 4 + 3] += hv * ww.w;
            }
        }

        float wn = g_w[node];
#pragma unroll
        for (int j = 0; j < HID; j++) acc[j] = wn * ftanh(h3[j]);
    }

    // ---- block reduction of acc[16] ----
    unsigned m = 0xffffffffu;
#pragma unroll
    for (int j = 0; j < HID; j++) {
#pragma unroll
        for (int off = 16; off > 0; off >>= 1)
            acc[j] += __shfl_down_sync(m, acc[j], off);
    }
    int warp = tid >> 5;
    int lane = tid & 31;
    if (lane == 0) {
#pragma unroll
        for (int j = 0; j < HID; j++) sRed[warp * HID + j] = acc[j];
    }
    __syncthreads();
    if (tid < HID) {
        float s = 0.0f;
#pragma unroll
        for (int wp = 0; wp < MLP_BLOCK / 32; wp++) s += sRed[wp * HID + tid];
        g_part[blockIdx.x * HID + tid] = s;
    }
}

__global__ void final_kernel(const float* __restrict__ Wc, const float* __restrict__ bc,
                             float* __restrict__ out, int nblocks, float inv_n) {
    __shared__ float s[128];
    int tid = threadIdx.x;
    int h = tid & (HID - 1);
    int g = tid >> 4;  // 0..7
    float v = 0.0f;
    for (int b = g; b < nblocks; b += 8) v += g_part[b * HID + h];
    s[tid] = v;
    __syncthreads();
    if (tid < HID) {
        float a = 0.0f;
#pragma unroll
        for (int gg = 0; gg < 8; gg++) a += s[gg * HID + tid];
        s[tid] = a * Wc[tid];  // each thread only reads column tid, then writes s[tid]: safe
    }
    __syncthreads();
    if (tid == 0) {
        float z = 0.0f;
#pragma unroll
        for (int j = 0; j < HID; j++) z += s[j];
        z = z * inv_n + bc[0];
        out[0] = 1.0f / (1.0f + __expf(-z));
    }
}

extern "C" void kernel_launch(void* const* d_in, const int* in_sizes, int n_in,
                              void* d_out, int out_size) {
    const float* x    = (const float*)d_in[0];
    const int*   esrc = (const int*)  d_in[1];
    const int*   edst = (const int*)  d_in[2];
    const float* W1   = (const float*)d_in[3];
    const float* b1   = (const float*)d_in[4];
    const float* W2   = (const float*)d_in[5];
    const float* b2   = (const float*)d_in[6];
    const float* W3   = (const float*)d_in[7];
    const float* b3   = (const float*)d_in[8];
    const float* Wc   = (const float*)d_in[9];
    const float* bc   = (const float*)d_in[10];
    float* out = (float*)d_out;

    int n = in_sizes[0] / ND;
    int e = in_sizes[1];
    if (n > N_MAX) n = N_MAX;

    zero_kernel<<<(n + 255) / 256, 256>>>(n);
    deg_kernel<<<(e + 255) / 256, 256>>>(esrc, e);
    w_kernel<<<(e + 255) / 256, 256>>>(esrc, edst, e);

    int nb = (n + MLP_BLOCK - 1) / MLP_BLOCK;
    mlp_kernel<<<nb, MLP_BLOCK>>>(x, W1, b1, W2, b2, W3, b3, n);
    final_kernel<<<1, 128>>>(Wc, bc, out, nb, 1.0f / (float)n);
}

// round 2
// speedup vs baseline: 1.2721x; 1.2721x over previous
#include <cuda_runtime.h>

#define ND 128
#define HID 16
#define N_MAX 100000

typedef unsigned long long u64;

// Scratch (device globals; no allocs allowed)
__device__ __align__(16) float g_deg[N_MAX];
__device__ __align__(16) float g_w[N_MAX];
__device__ __align__(16) float g_t[N_MAX * HID];
__device__ __align__(16) float g_agg[HID];

#define FMA2(d, a, b) \
    asm("fma.rn.f32x2 %0, %1, %2, %3;" : "=l"(d) : "l"(a), "l"(b), "l"(d))
#define PACK2(d, s) \
    asm("mov.b64 %0, {%1, %1};" : "=l"(d) : "r"(__float_as_uint(s)))
#define UNPACK2(lo, hi, s) \
    asm("mov.b64 {%0, %1}, %2;" : "=r"(lo), "=r"(hi) : "l"(s))

__device__ __forceinline__ float ftanh(float v) {
    return 1.0f - __fdividef(2.0f, __expf(2.0f * v) + 1.0f);
}

// ---------------- K0: zero scratch ----------------
__global__ void zero_kernel(int n4) {
    int i = blockIdx.x * blockDim.x + threadIdx.x;
    if (i < n4) {
        ((float4*)g_deg)[i] = make_float4(0.f, 0.f, 0.f, 0.f);
        ((float4*)g_w)[i]   = make_float4(0.f, 0.f, 0.f, 0.f);
    }
    if (blockIdx.x == 0 && threadIdx.x < HID) g_agg[threadIdx.x] = 0.f;
}

// ---------------- K1: fused MLP (blocks [0,nMlp)) + deg scatter (rest) ----
#define TPB 256
#define MLP_NPT 2
#define DEG_EPT 4

__global__ void __launch_bounds__(TPB) fused1_kernel(
    const float* __restrict__ x,
    const float* __restrict__ W1, const float* __restrict__ b1,
    const float* __restrict__ W2, const float* __restrict__ b2,
    const float* __restrict__ W3, const float* __restrict__ b3,
    const int* __restrict__ esrc,
    int n, int e, int nMlpBlocks)
{
    __shared__ float4 sW1[ND * HID / 4];   // 512 float4 = 8KB
    __shared__ float4 sW2[HID * HID / 4];  // 64 float4
    __shared__ float4 sW3[HID * HID / 4];
    __shared__ u64 sb1[8], sb2[8], sb3[8];
    __shared__ float sRed[(TPB / 32) * HID];

    int tid = threadIdx.x;

    if (blockIdx.x >= nMlpBlocks) {
        // ---- degree scatter path ----
        int db = blockIdx.x - nMlpBlocks;
        int base = (db * TPB + tid) * DEG_EPT;
        if (base + DEG_EPT <= e) {
            int4 s4 = *(const int4*)(esrc + base);
            atomicAdd(&g_deg[s4.x], 1.0f);
            atomicAdd(&g_deg[s4.y], 1.0f);
            atomicAdd(&g_deg[s4.z], 1.0f);
            atomicAdd(&g_deg[s4.w], 1.0f);
        } else {
            for (int i = base; i < e; i++) atomicAdd(&g_deg[esrc[i]], 1.0f);
        }
        return;
    }

    // ---- MLP path: compute t[node][16] = tanh3(...) ----
    for (int i = tid; i < ND * HID / 4; i += TPB) sW1[i] = ((const float4*)W1)[i];
    if (tid < HID * HID / 4) {
        sW2[tid] = ((const float4*)W2)[tid];
        sW3[tid] = ((const float4*)W3)[tid];
    }
    if (tid < 8) {
        sb1[tid] = ((const u64*)b1)[tid];
        sb2[tid] = ((const u64*)b2)[tid];
        sb3[tid] = ((const u64*)b3)[tid];
    }
    __syncthreads();

    int node0 = blockIdx.x * (TPB * MLP_NPT) + tid;
    int node1 = node0 + TPB;
    int c0 = min(node0, n - 1);
    int c1 = min(node1, n - 1);

    const float4* xr0 = (const float4*)(x + (size_t)c0 * ND);
    const float4* xr1 = (const float4*)(x + (size_t)c1 * ND);

    u64 h0[8], h1v[8];
#pragma unroll
    for (int q = 0; q < 8; q++) { h0[q] = sb1[q]; h1v[q] = sb1[q]; }

    // layer 1: 128 -> 16, f32x2 packed
#pragma unroll 4
    for (int k4 = 0; k4 < ND / 4; k4++) {
        float4 xa = xr0[k4];
        float4 xb = xr1[k4];
        float xas[4] = {xa.x, xa.y, xa.z, xa.w};
        float xbs[4] = {xb.x, xb.y, xb.z, xb.w};
#pragma unroll
        for (int i = 0; i < 4; i++) {
            const ulonglong2* wr = (const ulonglong2*)(sW1 + (k4 * 4 + i) * 4);
            u64 xpa, xpb;
            PACK2(xpa, xas[i]);
            PACK2(xpb, xbs[i]);
#pragma unroll
            for (int q = 0; q < 4; q++) {
                ulonglong2 ww = wr[q];
                FMA2(h0[2 * q],     xpa, ww.x);
                FMA2(h0[2 * q + 1], xpa, ww.y);
                FMA2(h1v[2 * q],     xpb, ww.x);
                FMA2(h1v[2 * q + 1], xpb, ww.y);
            }
        }
    }

    float t0[HID], t1[HID];
#pragma unroll
    for (int q = 0; q < 8; q++) {
        unsigned lo, hi;
        UNPACK2(lo, hi, h0[q]);
        t0[2 * q] = ftanh(__uint_as_float(lo));
        t0[2 * q + 1] = ftanh(__uint_as_float(hi));
        UNPACK2(lo, hi, h1v[q]);
        t1[2 * q] = ftanh(__uint_as_float(lo));
        t1[2 * q + 1] = ftanh(__uint_as_float(hi));
    }

    // layer 2
    u64 a0[8], a1[8];
#pragma unroll
    for (int q = 0; q < 8; q++) { a0[q] = sb2[q]; a1[q] = sb2[q]; }
#pragma unroll
    for (int i = 0; i < HID; i++) {
        const ulonglong2* wr = (const ulonglong2*)(sW2 + i * 4);
        u64 p0, p1;
        PACK2(p0, t0[i]);
        PACK2(p1, t1[i]);
#pragma unroll
        for (int q = 0; q < 4; q++) {
            ulonglong2 ww = wr[q];
            FMA2(a0[2 * q],     p0, ww.x);
            FMA2(a0[2 * q + 1], p0, ww.y);
            FMA2(a1[2 * q],     p1, ww.x);
            FMA2(a1[2 * q + 1], p1, ww.y);
        }
    }
#pragma unroll
    for (int q = 0; q < 8; q++) {
        unsigned lo, hi;
        UNPACK2(lo, hi, a0[q]);
        t0[2 * q] = ftanh(__uint_as_float(lo));
        t0[2 * q + 1] = ftanh(__uint_as_float(hi));
        UNPACK2(lo, hi, a1[q]);
        t1[2 * q] = ftanh(__uint_as_float(lo));
        t1[2 * q + 1] = ftanh(__uint_as_float(hi));
    }

    // layer 3
#pragma unroll
    for (int q = 0; q < 8; q++) { a0[q] = sb3[q]; a1[q] = sb3[q]; }
#pragma unroll
    for (int i = 0; i < HID; i++) {
        const ulonglong2* wr = (const ulonglong2*)(sW3 + i * 4);
        u64 p0, p1;
        PACK2(p0, t0[i]);
        PACK2(p1, t1[i]);
#pragma unroll
        for (int q = 0; q < 4; q++) {
            ulonglong2 ww = wr[q];
            FMA2(a0[2 * q],     p0, ww.x);
            FMA2(a0[2 * q + 1], p0, ww.y);
            FMA2(a1[2 * q],     p1, ww.x);
            FMA2(a1[2 * q + 1], p1, ww.y);
        }
    }
#pragma unroll
    for (int q = 0; q < 8; q++) {
        unsigned lo, hi;
        UNPACK2(lo, hi, a0[q]);
        t0[2 * q] = ftanh(__uint_as_float(lo));
        t0[2 * q + 1] = ftanh(__uint_as_float(hi));
        UNPACK2(lo, hi, a1[q]);
        t1[2 * q] = ftanh(__uint_as_float(lo));
        t1[2 * q + 1] = ftanh(__uint_as_float(hi));
    }

    // store t rows (clamped dup writes carry identical values -> benign)
    float4* tr0 = (float4*)(g_t + (size_t)c0 * HID);
    float4* tr1 = (float4*)(g_t + (size_t)c1 * HID);
#pragma unroll
    for (int q = 0; q < 4; q++) {
        tr0[q] = make_float4(t0[4 * q], t0[4 * q + 1], t0[4 * q + 2], t0[4 * q + 3]);
        tr1[q] = make_float4(t1[4 * q], t1[4 * q + 1], t1[4 * q + 2], t1[4 * q + 3]);
    }
    (void)sRed;
}

// ---------------- K2: w scatter: w[dst] += 1/deg[src] ----------------
__global__ void w_kernel(const int* __restrict__ src, const int* __restrict__ dst, int e) {
    int base = (blockIdx.x * blockDim.x + threadIdx.x) * DEG_EPT;
    if (base + DEG_EPT <= e) {
        int4 s4 = *(const int4*)(src + base);
        int4 d4 = *(const int4*)(dst + base);
        atomicAdd(&g_w[d4.x], __fdividef(1.0f, __ldg(&g_deg[s4.x])));
        atomicAdd(&g_w[d4.y], __fdividef(1.0f, __ldg(&g_deg[s4.y])));
        atomicAdd(&g_w[d4.z], __fdividef(1.0f, __ldg(&g_deg[s4.z])));
        atomicAdd(&g_w[d4.w], __fdividef(1.0f, __ldg(&g_deg[s4.w])));
    } else {
        for (int i = base; i < e; i++)
            atomicAdd(&g_w[dst[i]], __fdividef(1.0f, __ldg(&g_deg[src[i]])));
    }
}

// ---------------- K3: weighted reduce: agg += sum_m w[m] * t[m] --------
#define R_TPB 256
__global__ void __launch_bounds__(R_TPB) reduce_kernel(int n) {
    __shared__ float sRed[(R_TPB / 32) * HID];
    int node = blockIdx.x * R_TPB + threadIdx.x;
    float acc[HID];
#pragma unroll
    for (int j = 0; j < HID; j++) acc[j] = 0.0f;

    if (node < n) {
        float wn = g_w[node];
        const float4* tr = (const float4*)(g_t + (size_t)node * HID);
#pragma unroll
        for (int q = 0; q < 4; q++) {
            float4 tv = tr[q];
            acc[4 * q]     = wn * tv.x;
            acc[4 * q + 1] = wn * tv.y;
            acc[4 * q + 2] = wn * tv.z;
            acc[4 * q + 3] = wn * tv.w;
        }
    }

    unsigned m = 0xffffffffu;
#pragma unroll
    for (int j = 0; j < HID; j++) {
#pragma unroll
        for (int off = 16; off > 0; off >>= 1)
            acc[j] += __shfl_down_sync(m, acc[j], off);
    }
    int warp = threadIdx.x >> 5;
    int lane = threadIdx.x & 31;
    if (lane == 0) {
#pragma unroll
        for (int j = 0; j < HID; j++) sRed[warp * HID + j] = acc[j];
    }
    __syncthreads();
    if (threadIdx.x < HID) {
        float s = 0.0f;
#pragma unroll
        for (int wp = 0; wp < R_TPB / 32; wp++) s += sRed[wp * HID + threadIdx.x];
        atomicAdd(&g_agg[threadIdx.x], s);
    }
}

// ---------------- K4: final sigmoid ----------------
__global__ void final_kernel(const float* __restrict__ Wc, const float* __restrict__ bc,
                             float* __restrict__ out, float inv_n) {
    if (threadIdx.x == 0) {
        float z = 0.0f;
#pragma unroll
        for (int j = 0; j < HID; j++) z += g_agg[j] * Wc[j];
        z = z * inv_n + bc[0];
        out[0] = 1.0f / (1.0f + __expf(-z));
    }
}

extern "C" void kernel_launch(void* const* d_in, const int* in_sizes, int n_in,
                              void* d_out, int out_size) {
    const float* x    = (const float*)d_in[0];
    const int*   esrc = (const int*)  d_in[1];
    const int*   edst = (const int*)  d_in[2];
    const float* W1   = (const float*)d_in[3];
    const float* b1   = (const float*)d_in[4];
    const float* W2   = (const float*)d_in[5];
    const float* b2   = (const float*)d_in[6];
    const float* W3   = (const float*)d_in[7];
    const float* b3   = (const float*)d_in[8];
    const float* Wc   = (const float*)d_in[9];
    const float* bc   = (const float*)d_in[10];
    float* out = (float*)d_out;

    int n = in_sizes[0] / ND;
    int e = in_sizes[1];
    if (n > N_MAX) n = N_MAX;

    int n4 = (n + 3) / 4;
    zero_kernel<<<(n4 + 255) / 256, 256>>>(n4);

    int nMlp = (n + TPB * MLP_NPT - 1) / (TPB * MLP_NPT);
    int nDeg = (e + TPB * DEG_EPT - 1) / (TPB * DEG_EPT);
    fused1_kernel<<<nMlp + nDeg, TPB>>>(x, W1, b1, W2, b2, W3, b3, esrc, n, e, nMlp);

    w_kernel<<<nDeg, TPB>>>(esrc, edst, e);

    reduce_kernel<<<(n + R_TPB - 1) / R_TPB, R_TPB>>>(n);
    final_kernel<<<1, 32>>>(Wc, bc, out, 1.0f / (float)n);
}

// round 3
// speedup vs baseline: 1.4495x; 1.1394x over previous
#include <cuda_runtime.h>

#define ND 128
#define HID 16
#define N_MAX 100000

typedef unsigned long long u64;

// Scratch (device globals; no allocs allowed)
__device__ __align__(16) float g_deg[N_MAX];
__device__ __align__(16) float g_s[N_MAX];   // s[m] = tanh3(x_m)·Wc
__device__ float g_acc;

#define FMA2(d, a, b) \
    asm("fma.rn.f32x2 %0, %1, %2, %3;" : "=l"(d) : "l"(a), "l"(b), "l"(d))
#define PACK2(d, s) \
    asm("mov.b64 %0, {%1, %1};" : "=l"(d) : "r"(__float_as_uint(s)))
#define UNPACK2(lo, hi, s) \
    asm("mov.b64 {%0, %1}, %2;" : "=r"(lo), "=r"(hi) : "l"(s))

__device__ __forceinline__ float ftanh(float v) {
    return 1.0f - __fdividef(2.0f, __expf(2.0f * v) + 1.0f);
}

// ---------------- K0: zero deg + acc ----------------
__global__ void zero_kernel(int n4) {
    int i = blockIdx.x * blockDim.x + threadIdx.x;
    if (i < n4) ((float4*)g_deg)[i] = make_float4(0.f, 0.f, 0.f, 0.f);
    if (i == 0) g_acc = 0.f;
}

// ---------------- K1: fused MLP->s (blocks [0,nMlp)) + deg scatter ------
#define TPB 256
#define MLP_NPT 2
#define DEG_EPT 4

__global__ void __launch_bounds__(TPB) fused1_kernel(
    const float* __restrict__ x,
    const float* __restrict__ W1, const float* __restrict__ b1,
    const float* __restrict__ W2, const float* __restrict__ b2,
    const float* __restrict__ W3, const float* __restrict__ b3,
    const float* __restrict__ Wc,
    const int* __restrict__ esrc,
    int n, int e, int nMlpBlocks)
{
    __shared__ float4 sW1[ND * HID / 4];   // 8KB
    __shared__ float4 sW2[HID * HID / 4];
    __shared__ float4 sW3[HID * HID / 4];
    __shared__ u64 sb1[8], sb2[8], sb3[8];
    __shared__ float sWc[HID];

    int tid = threadIdx.x;

    if (blockIdx.x >= nMlpBlocks) {
        // ---- degree scatter path ----
        int db = blockIdx.x - nMlpBlocks;
        int base = (db * TPB + tid) * DEG_EPT;
        if (base + DEG_EPT <= e) {
            int4 s4 = *(const int4*)(esrc + base);
            atomicAdd(&g_deg[s4.x], 1.0f);
            atomicAdd(&g_deg[s4.y], 1.0f);
            atomicAdd(&g_deg[s4.z], 1.0f);
            atomicAdd(&g_deg[s4.w], 1.0f);
        } else {
            for (int i = base; i < e; i++) atomicAdd(&g_deg[esrc[i]], 1.0f);
        }
        return;
    }

    // ---- MLP path ----
    for (int i = tid; i < ND * HID / 4; i += TPB) sW1[i] = ((const float4*)W1)[i];
    if (tid < HID * HID / 4) {
        sW2[tid] = ((const float4*)W2)[tid];
        sW3[tid] = ((const float4*)W3)[tid];
    }
    if (tid < 8) {
        sb1[tid] = ((const u64*)b1)[tid];
        sb2[tid] = ((const u64*)b2)[tid];
        sb3[tid] = ((const u64*)b3)[tid];
    }
    if (tid < HID) sWc[tid] = Wc[tid];
    __syncthreads();

    int node0 = blockIdx.x * (TPB * MLP_NPT) + tid;
    int node1 = node0 + TPB;
    int c0 = min(node0, n - 1);
    int c1 = min(node1, n - 1);

    const float4* xr0 = (const float4*)(x + (size_t)c0 * ND);
    const float4* xr1 = (const float4*)(x + (size_t)c1 * ND);

    u64 h0[8], h1v[8];
#pragma unroll
    for (int q = 0; q < 8; q++) { h0[q] = sb1[q]; h1v[q] = sb1[q]; }

    // layer 1: 128 -> 16, f32x2 packed, 2 nodes/thread
#pragma unroll 4
    for (int k4 = 0; k4 < ND / 4; k4++) {
        float4 xa = xr0[k4];
        float4 xb = xr1[k4];
        float xas[4] = {xa.x, xa.y, xa.z, xa.w};
        float xbs[4] = {xb.x, xb.y, xb.z, xb.w};
#pragma unroll
        for (int i = 0; i < 4; i++) {
            const ulonglong2* wr = (const ulonglong2*)(sW1 + (k4 * 4 + i) * 4);
            u64 xpa, xpb;
            PACK2(xpa, xas[i]);
            PACK2(xpb, xbs[i]);
#pragma unroll
            for (int q = 0; q < 4; q++) {
                ulonglong2 ww = wr[q];
                FMA2(h0[2 * q],      xpa, ww.x);
                FMA2(h0[2 * q + 1],  xpa, ww.y);
                FMA2(h1v[2 * q],     xpb, ww.x);
                FMA2(h1v[2 * q + 1], xpb, ww.y);
            }
        }
    }

    float t0[HID], t1[HID];
#pragma unroll
    for (int q = 0; q < 8; q++) {
        unsigned lo, hi;
        UNPACK2(lo, hi, h0[q]);
        t0[2 * q] = ftanh(__uint_as_float(lo));
        t0[2 * q + 1] = ftanh(__uint_as_float(hi));
        UNPACK2(lo, hi, h1v[q]);
        t1[2 * q] = ftanh(__uint_as_float(lo));
        t1[2 * q + 1] = ftanh(__uint_as_float(hi));
    }

    // layer 2
    u64 a0[8], a1[8];
#pragma unroll
    for (int q = 0; q < 8; q++) { a0[q] = sb2[q]; a1[q] = sb2[q]; }
#pragma unroll
    for (int i = 0; i < HID; i++) {
        const ulonglong2* wr = (const ulonglong2*)(sW2 + i * 4);
        u64 p0, p1;
        PACK2(p0, t0[i]);
        PACK2(p1, t1[i]);
#pragma unroll
        for (int q = 0; q < 4; q++) {
            ulonglong2 ww = wr[q];
            FMA2(a0[2 * q],     p0, ww.x);
            FMA2(a0[2 * q + 1], p0, ww.y);
            FMA2(a1[2 * q],     p1, ww.x);
            FMA2(a1[2 * q + 1], p1, ww.y);
        }
    }
#pragma unroll
    for (int q = 0; q < 8; q++) {
        unsigned lo, hi;
        UNPACK2(lo, hi, a0[q]);
        t0[2 * q] = ftanh(__uint_as_float(lo));
        t0[2 * q + 1] = ftanh(__uint_as_float(hi));
        UNPACK2(lo, hi, a1[q]);
        t1[2 * q] = ftanh(__uint_as_float(lo));
        t1[2 * q + 1] = ftanh(__uint_as_float(hi));
    }

    // layer 3
#pragma unroll
    for (int q = 0; q < 8; q++) { a0[q] = sb3[q]; a1[q] = sb3[q]; }
#pragma unroll
    for (int i = 0; i < HID; i++) {
        const ulonglong2* wr = (const ulonglong2*)(sW3 + i * 4);
        u64 p0, p1;
        PACK2(p0, t0[i]);
        PACK2(p1, t1[i]);
#pragma unroll
        for (int q = 0; q < 4; q++) {
            ulonglong2 ww = wr[q];
            FMA2(a0[2 * q],     p0, ww.x);
            FMA2(a0[2 * q + 1], p0, ww.y);
            FMA2(a1[2 * q],     p1, ww.x);
            FMA2(a1[2 * q + 1], p1, ww.y);
        }
    }

    // tanh + contract with Wc -> scalar per node
    float s0 = 0.f, s1 = 0.f;
#pragma unroll
    for (int q = 0; q < 8; q++) {
        unsigned lo, hi;
        UNPACK2(lo, hi, a0[q]);
        s0 += ftanh(__uint_as_float(lo)) * sWc[2 * q];
        s0 += ftanh(__uint_as_float(hi)) * sWc[2 * q + 1];
        UNPACK2(lo, hi, a1[q]);
        s1 += ftanh(__uint_as_float(lo)) * sWc[2 * q];
        s1 += ftanh(__uint_as_float(hi)) * sWc[2 * q + 1];
    }

    // duplicate clamped writes carry identical values -> benign
    g_s[c0] = s0;
    g_s[c1] = s1;
}

// ---------------- K2: edge dot: acc += s[dst] / deg[src] ----------------
#define E_TPB 256
#define E_EPT 8

__global__ void __launch_bounds__(E_TPB) edge_dot_kernel(
    const int* __restrict__ src, const int* __restrict__ dst, int e)
{
    __shared__ float sRed[E_TPB / 32];
    int tid = threadIdx.x;
    int base = (blockIdx.x * E_TPB + tid) * E_EPT;
    float acc = 0.f;

    if (base + E_EPT <= e) {
        int4 sa = *(const int4*)(src + base);
        int4 sb = *(const int4*)(src + base + 4);
        int4 da = *(const int4*)(dst + base);
        int4 db = *(const int4*)(dst + base + 4);
        // issue all 16 gathers up front for MLP
        float dg0 = __ldg(&g_deg[sa.x]), dg1 = __ldg(&g_deg[sa.y]);
        float dg2 = __ldg(&g_deg[sa.z]), dg3 = __ldg(&g_deg[sa.w]);
        float dg4 = __ldg(&g_deg[sb.x]), dg5 = __ldg(&g_deg[sb.y]);
        float dg6 = __ldg(&g_deg[sb.z]), dg7 = __ldg(&g_deg[sb.w]);
        float sv0 = __ldg(&g_s[da.x]), sv1 = __ldg(&g_s[da.y]);
        float sv2 = __ldg(&g_s[da.z]), sv3 = __ldg(&g_s[da.w]);
        float sv4 = __ldg(&g_s[db.x]), sv5 = __ldg(&g_s[db.y]);
        float sv6 = __ldg(&g_s[db.z]), sv7 = __ldg(&g_s[db.w]);
        acc += sv0 * __frcp_rn(dg0);
        acc += sv1 * __frcp_rn(dg1);
        acc += sv2 * __frcp_rn(dg2);
        acc += sv3 * __frcp_rn(dg3);
        acc += sv4 * __frcp_rn(dg4);
        acc += sv5 * __frcp_rn(dg5);
        acc += sv6 * __frcp_rn(dg6);
        acc += sv7 * __frcp_rn(dg7);
    } else {
        for (int i = base; i < e; i++)
            acc += __ldg(&g_s[dst[i]]) * __frcp_rn(__ldg(&g_deg[src[i]]));
    }

    // warp + block reduce, one atomic per block
    unsigned m = 0xffffffffu;
#pragma unroll
    for (int off = 16; off > 0; off >>= 1)
        acc += __shfl_down_sync(m, acc, off);
    if ((tid & 31) == 0) sRed[tid >> 5] = acc;
    __syncthreads();
    if (tid < E_TPB / 32) {
        float v = sRed[tid];
#pragma unroll
        for (int off = (E_TPB / 64); off > 0; off >>= 1)
            v += __shfl_down_sync(m, v, off);
        if (tid == 0) atomicAdd(&g_acc, v);
    }
}

// ---------------- K3: final sigmoid ----------------
__global__ void final_kernel(const float* __restrict__ bc,
                             float* __restrict__ out, float inv_n) {
    if (threadIdx.x == 0) {
        float z = g_acc * inv_n + bc[0];
        out[0] = 1.0f / (1.0f + __expf(-z));
    }
}

extern "C" void kernel_launch(void* const* d_in, const int* in_sizes, int n_in,
                              void* d_out, int out_size) {
    const float* x    = (const float*)d_in[0];
    const int*   esrc = (const int*)  d_in[1];
    const int*   edst = (const int*)  d_in[2];
    const float* W1   = (const float*)d_in[3];
    const float* b1   = (const float*)d_in[4];
    const float* W2   = (const float*)d_in[5];
    const float* b2   = (const float*)d_in[6];
    const float* W3   = (const float*)d_in[7];
    const float* b3   = (const float*)d_in[8];
    const float* Wc   = (const float*)d_in[9];
    const float* bc   = (const float*)d_in[10];
    float* out = (float*)d_out;

    int n = in_sizes[0] / ND;
    int e = in_sizes[1];
    if (n > N_MAX) n = N_MAX;

    int n4 = (n + 3) / 4;
    zero_kernel<<<(n4 + 255) / 256, 256>>>(n4);

    int nMlp = (n + TPB * MLP_NPT - 1) / (TPB * MLP_NPT);
    int nDeg = (e + TPB * DEG_EPT - 1) / (TPB * DEG_EPT);
    fused1_kernel<<<nMlp + nDeg, TPB>>>(x, W1, b1, W2, b2, W3, b3, Wc, esrc, n, e, nMlp);

    edge_dot_kernel<<<(e + E_TPB * E_EPT - 1) / (E_TPB * E_EPT), E_TPB>>>(esrc, edst, e);

    final_kernel<<<1, 32>>>(bc, out, 1.0f / (float)n);
}